// round 17
// baseline (speedup 1.0000x reference)
#include <cuda_runtime.h>
#include <cstdint>

// nu_grid_sampler: out[b,c,n] = x[b,c,px,py], x:(8,128,256,256) f32,
// coords:(8,32768,2) f32, out:(8,128,32768) f32.
//
// R17: line-sorted direct gather (R14/R15 winner) with a j-half split to get
// 2 blocks/SM. Counting sort buckets = (j>=16384, idx>>5) -> 4096 buckets:
// each batch's sorted array has half0 (j<16384) then half1, each line-sorted.
// Gather: grid (1024 planes x 2 halves), 64KB smem obuf, launch_bounds(1024,2)
// -> ~100% occupancy hides gather latency + flush tails. Sort: proven 4-launch
// chain (memset + hist + prefix + scatter) extended to 4096 buckets.

#define GS_B 8
#define GS_C 128
#define GS_NX 256
#define GS_NY 256
#define GS_N 32768
#define GS_HALF_N (GS_N / 2)        // 16384
#define GS_PIX (GS_NX * GS_NY)      // 65536
#define NBUCK 4096                   // (j-half, 128B line)
#define K2_THREADS 1024
#define HITERS (GS_HALF_N / K2_THREADS)   // 16
#define OBUF_BYTES (GS_HALF_N * 4)        // 64KB

__device__ unsigned g_idx[GS_B * GS_N];      // raw pixel idx per point
__device__ unsigned g_sorted[GS_B * GS_N];   // idx | (local_j<<16)
__device__ int g_hist[GS_B * NBUCK];
__device__ int g_cursor[GS_B * NBUCK];

__device__ __forceinline__ unsigned compute_idx(float cy, float cx) {
    float pxf = fminf(fmaxf(cx * (float)(GS_NX - 1), 0.0f), (float)GS_NX);
    float pyf = fminf(fmaxf(cy * (float)(GS_NY - 1), 0.0f), (float)GS_NY);
    int idx = (int)pxf * GS_NY + (int)pyf;
    return (unsigned)min(idx, GS_PIX - 1);   // take_along_axis clamp
}

__device__ __forceinline__ int bucket_of(unsigned idx, int j) {
    return ((j >> 14) << 11) | (int)(idx >> 5);
}

__global__ __launch_bounds__(1024)
void hist_kernel(const float* __restrict__ coords) {
    __shared__ int lh[NBUCK];       // 16KB
    const int t = threadIdx.x;
    const int b = blockIdx.y;
    const int j = blockIdx.x * 1024 + t;
    #pragma unroll
    for (int q = 0; q < 4; ++q) lh[t + q * 1024] = 0;
    __syncthreads();
    float2 co = reinterpret_cast<const float2*>(coords)[(size_t)b * GS_N + j];
    unsigned idx = compute_idx(co.x, co.y);
    g_idx[b * GS_N + j] = idx;
    atomicAdd(&lh[bucket_of(idx, j)], 1);
    __syncthreads();
    #pragma unroll
    for (int q = 0; q < 4; ++q) {
        int s = t + q * 1024;
        if (lh[s]) atomicAdd(&g_hist[b * NBUCK + s], lh[s]);
    }
}

__global__ __launch_bounds__(1024)
void prefix_kernel() {            // one block per batch: exclusive scan of 4096
    __shared__ int sc[NBUCK];     // 16KB
    __shared__ int ps[1024];
    const int t = threadIdx.x;
    const int b = blockIdx.x;
    #pragma unroll
    for (int q = 0; q < 4; ++q) sc[t + q * 1024] = g_hist[b * NBUCK + t + q * 1024];
    __syncthreads();
    int quad = sc[4 * t] + sc[4 * t + 1] + sc[4 * t + 2] + sc[4 * t + 3];
    ps[t] = quad;
    __syncthreads();
    for (int off = 1; off < 1024; off <<= 1) {      // Hillis-Steele inclusive
        int v = (t >= off) ? ps[t - off] : 0;
        __syncthreads();
        ps[t] += v;
        __syncthreads();
    }
    int base = ps[t] - quad;                         // exclusive over quads
    g_cursor[b * NBUCK + 4 * t]     = base;
    g_cursor[b * NBUCK + 4 * t + 1] = base + sc[4 * t];
    g_cursor[b * NBUCK + 4 * t + 2] = base + sc[4 * t] + sc[4 * t + 1];
    g_cursor[b * NBUCK + 4 * t + 3] = base + sc[4 * t] + sc[4 * t + 1] + sc[4 * t + 2];
}

__global__ __launch_bounds__(1024)
void scatter_kernel() {
    __shared__ int lh[NBUCK];       // 16KB
    __shared__ int lbase[NBUCK];    // 16KB
    const int t = threadIdx.x;
    const int b = blockIdx.y;
    const int j = blockIdx.x * 1024 + t;
    #pragma unroll
    for (int q = 0; q < 4; ++q) lh[t + q * 1024] = 0;
    __syncthreads();
    unsigned idx = g_idx[b * GS_N + j];
    int s = bucket_of(idx, j);
    int r = atomicAdd(&lh[s], 1);
    __syncthreads();
    #pragma unroll
    for (int q = 0; q < 4; ++q) {
        int u = t + q * 1024;
        if (lh[u]) lbase[u] = atomicAdd(&g_cursor[b * NBUCK + u], lh[u]);
    }
    __syncthreads();
    // store local j (j mod 16384) so gather indexes its 64KB half-obuf directly
    g_sorted[b * GS_N + lbase[s] + r] = idx | ((unsigned)(j & (GS_HALF_N - 1)) << 16);
}

__global__ __launch_bounds__(K2_THREADS, 2)
void gather_kernel(const float* __restrict__ x, float* __restrict__ out) {
    extern __shared__ float obuf[];              // 16384 floats = 64KB
    const int tid  = threadIdx.x;
    const int bc   = blockIdx.x;                 // b*128 + c
    const int half = blockIdx.y;                 // j-half
    const int b    = bc >> 7;

    const float* __restrict__ plane   = x + ((size_t)bc << 16);
    const unsigned* __restrict__ ents = g_sorted + b * GS_N + half * GS_HALF_N;

    // 16 iterations: coalesced entry load, near-coalesced line-sorted gather,
    // STS scatter into the 64KB half-plane obuf.
    #pragma unroll 4
    for (int it = 0; it < HITERS; ++it) {
        unsigned e = __ldg(ents + (it << 10) + tid);
        obuf[e >> 16] = __ldg(plane + (e & 0xFFFFu));
    }
    __syncthreads();

    // Dense float4 flush of the contiguous 64KB half (STGs retire async).
    float* __restrict__ ob = out + ((size_t)bc << 15) + (half << 14);
    #pragma unroll
    for (int q = 0; q < GS_HALF_N / (K2_THREADS * 4); ++q) {   // 4 iters
        int o = (q * K2_THREADS + tid) * 4;
        float4 v = *reinterpret_cast<const float4*>(&obuf[o]);
        *reinterpret_cast<float4*>(&ob[o]) = v;
    }
}

extern "C" void kernel_launch(void* const* d_in, const int* in_sizes, int n_in,
                              void* d_out, int out_size) {
    const float* x      = (const float*)d_in[0];   // (8,128,256,256) f32
    const float* coords = (const float*)d_in[1];   // (8,32768,2) f32
    float* out          = (float*)d_out;           // (8,128,32768) f32

    static void* hist_addr = nullptr;
    static int init_done = 0;
    if (!init_done) {
        cudaFuncSetAttribute(gather_kernel,
                             cudaFuncAttributeMaxDynamicSharedMemorySize,
                             OBUF_BYTES);
        cudaGetSymbolAddress(&hist_addr, g_hist);
        init_done = 1;
    }

    cudaMemsetAsync(hist_addr, 0, GS_B * NBUCK * sizeof(int));
    hist_kernel<<<dim3(GS_N / 1024, GS_B), 1024>>>(coords);
    prefix_kernel<<<GS_B, 1024>>>();
    scatter_kernel<<<dim3(GS_N / 1024, GS_B), 1024>>>();
    gather_kernel<<<dim3(GS_B * GS_C, 2), K2_THREADS, OBUF_BYTES>>>(x, out);
}